// round 1
// baseline (speedup 1.0000x reference)
#include <cuda_runtime.h>
#include <math.h>
#include <stdint.h>

#define NH    16
#define NKV   8
#define HD    128
#define CEMB  2048
#define BATCH 2
#define TSEQ  2048
#define MROWS (BATCH * TSEQ)
#define KVC   (NKV * HD)   // 1024

// ---------------- scratch (static device allocations are allowed) ------------
__device__ float g_q [MROWS * CEMB];   // raw q  = x@wq
__device__ float g_k [MROWS * KVC];    // raw k  = x@wk
__device__ float g_v [MROWS * KVC];    // v (updated in place with ve-gate)
__device__ float g_qn[MROWS * CEMB];   // rmsnorm(rope(q))
__device__ float g_kn[MROWS * KVC];    // rmsnorm(rope(shifted k))
__device__ float g_y [MROWS * CEMB];   // attention output * attn_gate
__device__ float g_ag[MROWS * NH];     // attn gate

// ---------------- classic SGEMM: C[M,N] = A[M,K] @ B[K,N] (row-major) --------
// BM=BN=128, BK=8, TM=TN=8, 256 threads. M,N,K multiples of 128/128/8.
__global__ __launch_bounds__(256) void sgemm128(
    int M, int N, int K,
    const float* __restrict__ A, const float* __restrict__ B,
    float* __restrict__ C, const float* __restrict__ scale_ptr)
{
    __shared__ float As[8][128];
    __shared__ float Bs[8][128];
    const int tid = threadIdx.x;
    const float* Ab = A + (size_t)blockIdx.y * 128 * K;
    const float* Bb = B + blockIdx.x * 128;
    float* Cb = C + (size_t)blockIdx.y * 128 * N + blockIdx.x * 128;

    const int trow = tid >> 4;          // 0..15
    const int tcol = tid & 15;          // 0..15
    const int aRow = tid >> 1;          // 0..127
    const int aCol = (tid & 1) * 4;     // 0 or 4
    const int bRow = tid >> 5;          // 0..7
    const int bCol = (tid & 31) * 4;    // 0..124

    float acc[8][8];
#pragma unroll
    for (int i = 0; i < 8; i++)
#pragma unroll
        for (int j = 0; j < 8; j++) acc[i][j] = 0.f;

    for (int k0 = 0; k0 < K; k0 += 8) {
        float4 a = *(const float4*)(Ab + (size_t)aRow * K + k0 + aCol);
        As[aCol + 0][aRow] = a.x;
        As[aCol + 1][aRow] = a.y;
        As[aCol + 2][aRow] = a.z;
        As[aCol + 3][aRow] = a.w;
        *(float4*)(&Bs[bRow][bCol]) = *(const float4*)(Bb + (size_t)(k0 + bRow) * N + bCol);
        __syncthreads();
#pragma unroll
        for (int kk = 0; kk < 8; kk++) {
            float ra[8], rb[8];
            *(float4*)(ra)     = *(float4*)(&As[kk][trow * 8]);
            *(float4*)(ra + 4) = *(float4*)(&As[kk][trow * 8 + 4]);
            *(float4*)(rb)     = *(float4*)(&Bs[kk][tcol * 8]);
            *(float4*)(rb + 4) = *(float4*)(&Bs[kk][tcol * 8 + 4]);
#pragma unroll
            for (int i = 0; i < 8; i++)
#pragma unroll
                for (int j = 0; j < 8; j++) acc[i][j] += ra[i] * rb[j];
        }
        __syncthreads();
    }

    float sc = scale_ptr ? (1.0f + scale_ptr[0]) : 1.0f;
#pragma unroll
    for (int i = 0; i < 8; i++) {
        float4 v0 = make_float4(acc[i][0] * sc, acc[i][1] * sc, acc[i][2] * sc, acc[i][3] * sc);
        float4 v1 = make_float4(acc[i][4] * sc, acc[i][5] * sc, acc[i][6] * sc, acc[i][7] * sc);
        float* cr = Cb + (size_t)(trow * 8 + i) * N + tcol * 8;
        *(float4*)(cr)     = v0;
        *(float4*)(cr + 4) = v1;
    }
}

// ---------------- ve gate + v update + attn gate ----------------------------
__global__ __launch_bounds__(128) void gates_kernel(
    const float* __restrict__ x, const float* __restrict__ ve,
    const float* __restrict__ wvg /*[32,8]*/, const float* __restrict__ wag /*[12,16]*/)
{
    const int bt  = blockIdx.x;
    const int tid = threadIdx.x;
    __shared__ float xs[32];
    __shared__ float sg[8];

    if (tid < 32) xs[tid] = x[(size_t)bt * CEMB + tid];
    __syncthreads();

    if (tid < 8) {
        float s = 0.f;
#pragma unroll
        for (int c = 0; c < 32; c++) s += xs[c] * wvg[c * 8 + tid];
        sg[tid] = 2.0f / (1.0f + __expf(-s));
    } else if (tid >= 32 && tid < 48) {
        int h = tid - 32;
        float s = 0.f;
#pragma unroll
        for (int c = 0; c < 12; c++) s += xs[c] * wag[c * 16 + h];
        g_ag[(size_t)bt * NH + h] = 1.0f / (1.0f + __expf(-s));
    }
    __syncthreads();

    for (int i = tid; i < KVC; i += 128)
        g_v[(size_t)bt * KVC + i] += sg[i >> 7] * ve[(size_t)bt * KVC + i];
}

// ---------------- k time-shift + RoPE + RMSNorm (one warp per head-vector) --
__global__ __launch_bounds__(128) void ropenorm_kernel(
    const float* __restrict__ cosb, const float* __restrict__ sinb)
{
    const int gw   = blockIdx.x * 4 + (threadIdx.x >> 5);
    const int lane = threadIdx.x & 31;
    const int bt = gw / 24;
    const int hh = gw % 24;
    const int t  = bt % TSEQ;

    const float c0 = cosb[t * 64 + lane];
    const float c1 = cosb[t * 64 + lane + 32];
    const float s0 = sinb[t * 64 + lane];
    const float s1 = sinb[t * 64 + lane + 32];

    float t1a, t1b, t2a, t2b;
    float* dst;
    if (hh < 16) {
        const float* base = g_q + (size_t)bt * CEMB + hh * HD;
        t1a = base[lane];      t1b = base[lane + 32];
        t2a = base[64 + lane]; t2b = base[96 + lane];
        dst = g_qn + (size_t)bt * CEMB + hh * HD;
    } else {
        const int j = hh - 16;
        const float* base = g_k + (size_t)bt * KVC + j * HD;
        const int bt2 = (t == 0) ? bt : (bt - 1);           // shift second half
        const float* base2 = g_k + (size_t)bt2 * KVC + j * HD;
        t1a = base [lane];      t1b = base [lane + 32];
        t2a = base2[64 + lane]; t2b = base2[96 + lane];
        dst = g_kn + (size_t)bt * KVC + j * HD;
    }

    float o1a =  t1a * c0 + t2a * s0;
    float o1b =  t1b * c1 + t2b * s1;
    float o2a = -t1a * s0 + t2a * c0;
    float o2b = -t1b * s1 + t2b * c1;

    float ss = o1a * o1a + o1b * o1b + o2a * o2a + o2b * o2b;
#pragma unroll
    for (int o = 16; o > 0; o >>= 1) ss += __shfl_xor_sync(0xffffffffu, ss, o);
    const float r = rsqrtf(ss * (1.0f / 128.0f) + 1.1920929e-7f);

    dst[lane]      = o1a * r;
    dst[lane + 32] = o1b * r;
    dst[64 + lane] = o2a * r;
    dst[96 + lane] = o2b * r;
}

// ---------------- sliding-window GQA flash attention -------------------------
// Block: 64 q-rows of one (b,h). 128 threads: thread = (row = tid>>1, half = tid&1).
// 64-float q and 64-float acc in registers; 32-key K/V tiles in smem.
__global__ __launch_bounds__(128) void attn_kernel(const int* __restrict__ wsp)
{
    __shared__ float Ksm[32 * 128];
    __shared__ float Vsm[32 * 128];

    const int tile = blockIdx.x;          // 0 .. T/64-1
    const int bh   = blockIdx.y;          // 0 .. B*NH-1
    const int b = bh / NH, h = bh % NH;
    const int kvh = h >> 1;               // rep = 2
    const int tid = threadIdx.x;
    const int row = tid >> 1;
    const int dh  = (tid & 1) * 64;
    const int q0  = tile * 64;
    const int qi  = q0 + row;

    int WS = wsp[0];
    if (WS <= 0 || WS > (1 << 20)) WS = 1024;   // dtype-safety fallback
    const float scale = 0.088388347648318447f;  // 1/sqrt(128)

    float qreg[64];
    const float* qp = g_qn + (size_t)(b * TSEQ + qi) * CEMB + h * HD + dh;
#pragma unroll
    for (int i = 0; i < 64; i += 4) *(float4*)(qreg + i) = *(const float4*)(qp + i);

    float acc[64];
#pragma unroll
    for (int i = 0; i < 64; i++) acc[i] = 0.f;
    float m = -INFINITY, l = 0.f;

    int kmin = q0 - WS; if (kmin < 0) kmin = 0;
    const int kt0 = kmin & ~31;

    for (int kt = kt0; kt <= q0 + 63; kt += 32) {
        __syncthreads();
        {
            const float* Kb = g_kn + (size_t)(b * TSEQ + kt) * KVC + kvh * HD;
            const float* Vb = g_v  + (size_t)(b * TSEQ + kt) * KVC + kvh * HD;
#pragma unroll
            for (int i = 0; i < 8; i++) {
                const int f = (i * 128 + tid) * 4;
                const int r = f >> 7, c = f & 127;
                *(float4*)(Ksm + f) = *(const float4*)(Kb + (size_t)r * KVC + c);
                *(float4*)(Vsm + f) = *(const float4*)(Vb + (size_t)r * KVC + c);
            }
        }
        __syncthreads();

        for (int j = 0; j < 32; j++) {
            const int kj = kt + j;
            const bool valid = (kj <= qi) && (kj >= qi - WS);
            if (__all_sync(0xffffffffu, !valid)) continue;   // converged skip

            const float4* kr4 = (const float4*)(Ksm + j * 128 + dh);
            float sp0 = 0.f, sp1 = 0.f, sp2 = 0.f, sp3 = 0.f;
#pragma unroll
            for (int i = 0; i < 16; i++) {
                float4 kv = kr4[i];
                sp0 += qreg[4 * i]     * kv.x;
                sp1 += qreg[4 * i + 1] * kv.y;
                sp2 += qreg[4 * i + 2] * kv.z;
                sp3 += qreg[4 * i + 3] * kv.w;
            }
            float s = (sp0 + sp1) + (sp2 + sp3);
            s += __shfl_xor_sync(0xffffffffu, s, 1);         // full mask, all lanes
            if (!valid) continue;

            s *= scale;
            if (s > m) {                                      // rare rescale
                const float corr = __expf(m - s);
                m = s;
                l *= corr;
#pragma unroll
                for (int i = 0; i < 64; i++) acc[i] *= corr;
            }
            const float p = __expf(s - m);
            l += p;
            const float4* vr4 = (const float4*)(Vsm + j * 128 + dh);
#pragma unroll
            for (int i = 0; i < 16; i++) {
                float4 vv = vr4[i];
                acc[4 * i]     += p * vv.x;
                acc[4 * i + 1] += p * vv.y;
                acc[4 * i + 2] += p * vv.z;
                acc[4 * i + 3] += p * vv.w;
            }
        }
    }

    const float ag  = g_ag[(size_t)(b * TSEQ + qi) * NH + h];
    const float inv = ag / l;
    float* yp = g_y + (size_t)(b * TSEQ + qi) * CEMB + h * HD + dh;
#pragma unroll
    for (int i = 0; i < 64; i++) yp[i] = acc[i] * inv;
}

// ---------------- launcher ---------------------------------------------------
extern "C" void kernel_launch(void* const* d_in, const int* in_sizes, int n_in,
                              void* d_out, int out_size)
{
    const float* x     = (const float*)d_in[0];
    const float* ve    = (const float*)d_in[1];
    const float* cosb  = (const float*)d_in[2];
    const float* sinb  = (const float*)d_in[3];
    const float* wq    = (const float*)d_in[4];
    const float* wk    = (const float*)d_in[5];
    const float* wv    = (const float*)d_in[6];
    const float* wproj = (const float*)d_in[7];
    const float* wvg   = (const float*)d_in[8];
    const float* wag   = (const float*)d_in[9];
    const float* ps    = (const float*)d_in[10];
    const int*   wsp   = (const int*)  d_in[11];
    float* out = (float*)d_out;

    float *pq, *pk, *pv, *py;
    cudaGetSymbolAddress((void**)&pq, g_q);
    cudaGetSymbolAddress((void**)&pk, g_k);
    cudaGetSymbolAddress((void**)&pv, g_v);
    cudaGetSymbolAddress((void**)&py, g_y);

    // QKV projections
    sgemm128<<<dim3(CEMB / 128, MROWS / 128), 256>>>(MROWS, CEMB, CEMB, x, wq, pq, nullptr);
    sgemm128<<<dim3(KVC  / 128, MROWS / 128), 256>>>(MROWS, KVC,  CEMB, x, wk, pk, nullptr);
    sgemm128<<<dim3(KVC  / 128, MROWS / 128), 256>>>(MROWS, KVC,  CEMB, x, wv, pv, nullptr);

    // gates + v update
    gates_kernel<<<MROWS, 128>>>(x, ve, wvg, wag);

    // k shift + rope + rmsnorm (q and k)
    ropenorm_kernel<<<MROWS * 24 / 4, 128>>>(cosb, sinb);

    // sliding-window attention (+ attn gate)
    attn_kernel<<<dim3(TSEQ / 64, BATCH * NH), 128>>>(wsp);

    // output projection with (1 + proj_scalar)
    sgemm128<<<dim3(CEMB / 128, MROWS / 128), 256>>>(MROWS, CEMB, CEMB, py, wproj, out, ps);
}

// round 3
// speedup vs baseline: 1.5420x; 1.5420x over previous
#include <cuda_runtime.h>
#include <cuda_bf16.h>
#include <math.h>
#include <stdint.h>

#define NH    16
#define NKV   8
#define HD    128
#define CEMB  2048
#define BATCH 2
#define TSEQ  2048
#define MROWS (BATCH * TSEQ)
#define KVC   (NKV * HD)   // 1024

// ---------------- scratch ----------------------------------------------------
__device__ float g_q [MROWS * CEMB];
__device__ float g_k [MROWS * KVC];
__device__ float g_v [MROWS * KVC];
__device__ float g_qn[MROWS * CEMB];
__device__ float g_kn[MROWS * KVC];
__device__ float g_y [MROWS * CEMB];
__device__ float g_ag[MROWS * NH];

// split-bf16 operands: A rows have 4096 cols = [hi(2048) | lo(2048)]
__device__ __nv_bfloat16 g_x2 [MROWS * 2 * CEMB];
__device__ __nv_bfloat16 g_y2 [MROWS * 2 * CEMB];
// transposed split weights: [N rows hi][N rows lo] x K=2048 each
__device__ __nv_bfloat16 g_wqt[2 * CEMB * CEMB];
__device__ __nv_bfloat16 g_wkt[2 * KVC  * CEMB];
__device__ __nv_bfloat16 g_wvt[2 * KVC  * CEMB];
__device__ __nv_bfloat16 g_wpt[2 * CEMB * CEMB];

// ---------------- helpers ----------------------------------------------------
__device__ __forceinline__ uint32_t smem_u32(const void* p) {
    uint32_t a;
    asm("{ .reg .u64 t; cvta.to.shared.u64 t, %1; cvt.u32.u64 %0, t; }" : "=r"(a) : "l"(p));
    return a;
}
#define CP_ASYNC16(dst, src) \
    asm volatile("cp.async.cg.shared.global [%0], [%1], 16;" :: "r"(dst), "l"(src))
#define CP_COMMIT() asm volatile("cp.async.commit_group;" ::: "memory")
#define CP_WAIT1()  asm volatile("cp.async.wait_group 1;" ::: "memory")

__device__ __forceinline__ void ldm_x4(uint32_t& r0, uint32_t& r1, uint32_t& r2, uint32_t& r3,
                                       uint32_t addr) {
    asm volatile("ldmatrix.sync.aligned.m8n8.x4.shared.b16 {%0,%1,%2,%3}, [%4];"
                 : "=r"(r0), "=r"(r1), "=r"(r2), "=r"(r3) : "r"(addr));
}
__device__ __forceinline__ void mma_bf16(float& d0, float& d1, float& d2, float& d3,
                                         uint32_t a0, uint32_t a1, uint32_t a2, uint32_t a3,
                                         uint32_t b0, uint32_t b1) {
    asm volatile("mma.sync.aligned.m16n8k16.row.col.f32.bf16.bf16.f32 "
                 "{%0,%1,%2,%3}, {%4,%5,%6,%7}, {%8,%9}, {%0,%1,%2,%3};"
                 : "+f"(d0), "+f"(d1), "+f"(d2), "+f"(d3)
                 : "r"(a0), "r"(a1), "r"(a2), "r"(a3), "r"(b0), "r"(b1));
}

// ---------------- split conversion: fp32 [M][2048] -> bf16 [M][4096] hi|lo ---
__global__ __launch_bounds__(256) void conv_split(const float* __restrict__ in,
                                                  __nv_bfloat16* __restrict__ out)
{
    const int idx = (blockIdx.x * 256 + threadIdx.x) * 4;
    const int row = idx >> 11;
    const int col = idx & 2047;
    float4 v = *(const float4*)(in + (size_t)row * CEMB + col);
    __nv_bfloat16 h0 = __float2bfloat16(v.x), h1 = __float2bfloat16(v.y);
    __nv_bfloat16 h2 = __float2bfloat16(v.z), h3 = __float2bfloat16(v.w);
    __nv_bfloat16 l0 = __float2bfloat16(v.x - __bfloat162float(h0));
    __nv_bfloat16 l1 = __float2bfloat16(v.y - __bfloat162float(h1));
    __nv_bfloat16 l2 = __float2bfloat16(v.z - __bfloat162float(h2));
    __nv_bfloat16 l3 = __float2bfloat16(v.w - __bfloat162float(h3));
    __nv_bfloat16* base = out + (size_t)row * 4096;
    *(__nv_bfloat162*)(base + col)            = __nv_bfloat162(h0, h1);
    *(__nv_bfloat162*)(base + col + 2)        = __nv_bfloat162(h2, h3);
    *(__nv_bfloat162*)(base + 2048 + col)     = __nv_bfloat162(l0, l1);
    *(__nv_bfloat162*)(base + 2048 + col + 2) = __nv_bfloat162(l2, l3);
}

// ---------------- weight transpose + split: w[K=2048][N] -> wt[2N][2048] -----
__global__ __launch_bounds__(256) void conv_wt(const float* __restrict__ w,
                                               __nv_bfloat16* __restrict__ wt, int N)
{
    __shared__ float tile[32][33];
    const int n0 = blockIdx.x * 32, k0 = blockIdx.y * 32;
    const int tx = threadIdx.x, ty = threadIdx.y;   // (32, 8)
#pragma unroll
    for (int r = 0; r < 4; r++)
        tile[ty + 8 * r][tx] = w[(size_t)(k0 + ty + 8 * r) * N + n0 + tx];
    __syncthreads();
#pragma unroll
    for (int r = 0; r < 4; r++) {
        const int n = n0 + ty + 8 * r, k = k0 + tx;
        float v = tile[tx][ty + 8 * r];
        __nv_bfloat16 h = __float2bfloat16(v);
        __nv_bfloat16 l = __float2bfloat16(v - __bfloat162float(h));
        wt[(size_t)n * CEMB + k]       = h;
        wt[(size_t)(N + n) * CEMB + k] = l;
    }
}

// ---------------- mma.sync split-bf16 GEMM -----------------------------------
// C[4096][N] = A2(split hi|lo) @ Bt^T(split), 3-term accumulation folded into
// one 96-iter K loop. CTA 128x128, BK=64, 3-stage cp.async ring.
// 8 warps (4M x 2N), warp tile 32x64, mma.sync m16n8k16 bf16.
#define STAGE_BYTES 32768               // A 16KB + B 16KB
#define GSMEM_TOT   (3 * STAGE_BYTES)   // 98304

__global__ __launch_bounds__(256) void mma_gemm(
    const __nv_bfloat16* __restrict__ A2, const __nv_bfloat16* __restrict__ Bt,
    float* __restrict__ C, int N, const float* __restrict__ scale_ptr)
{
    extern __shared__ char smem[];
    const uint32_t sb = smem_u32(smem);
    const int tid  = threadIdx.x;
    const int wid  = tid >> 5, lane = tid & 31;
    const int wm   = wid >> 1, wn = wid & 1;
    const int m0   = blockIdx.y * 128;
    const int n0   = blockIdx.x * 128;

    // ---- load decomposition: 16B chunk c (0..7), base row r0 (0..31)
    const int c  = tid & 7;
    const int r0 = tid >> 3;

    const int NIT = 96;      // 3 terms x 32 BK64 steps

    auto load_stage = [&](int i) {
        const int s    = i % 3;
        const int term = i >> 5;
        const int k0   = (i & 31) * 64;
        const int aoff = (term == 2) ? 2048 : 0;
        const int brow = (term == 1) ? N : 0;
        const uint32_t da = sb + s * STAGE_BYTES;
        const uint32_t db = da + 16384;
        const __nv_bfloat16* Ap = A2 + (size_t)(m0 + r0) * 4096 + aoff + k0 + c * 8;
        const __nv_bfloat16* Bp = Bt + (size_t)(brow + n0 + r0) * 2048 + k0 + c * 8;
#pragma unroll
        for (int j = 0; j < 4; j++) {
            const int row = r0 + 32 * j;
            CP_ASYNC16(da + row * 128 + (((c ^ (row & 7))) << 4), Ap + (size_t)(32 * j) * 4096);
            CP_ASYNC16(db + row * 128 + (((c ^ (row & 7))) << 4), Bp + (size_t)(32 * j) * 2048);
        }
        CP_COMMIT();
    };

    // ---- per-lane ldmatrix row indices (fixed; chunk varies per k-step)
    const int lrow = lane & 15;       // row within 16-row tile group
    const int lhi  = lane >> 4;       // k-chunk select (0/1)

    int arow[2], brows[4];
#pragma unroll
    for (int mt = 0; mt < 2; mt++) arow[mt] = wm * 32 + mt * 16 + lrow;
#pragma unroll
    for (int nt = 0; nt < 4; nt++) brows[nt] = wn * 64 + nt * 16 + lrow;

    float acc[2][8][4];
#pragma unroll
    for (int mt = 0; mt < 2; mt++)
#pragma unroll
        for (int j = 0; j < 8; j++)
#pragma unroll
            for (int e = 0; e < 4; e++) acc[mt][j][e] = 0.f;

    load_stage(0);
    load_stage(1);

    for (int i = 0; i < NIT; i++) {
        CP_WAIT1();
        __syncthreads();
        if (i + 2 < NIT) load_stage(i + 2);

        const uint32_t sa = sb + (i % 3) * STAGE_BYTES;
        const uint32_t sB = sa + 16384;

#pragma unroll
        for (int kk = 0; kk < 4; kk++) {
            const int chunk = kk * 2 + lhi;
            uint32_t a[2][4];
#pragma unroll
            for (int mt = 0; mt < 2; mt++) {
                const int row = arow[mt];
                ldm_x4(a[mt][0], a[mt][1], a[mt][2], a[mt][3],
                       sa + row * 128 + ((chunk ^ (row & 7)) << 4));
            }
            uint32_t bt[4][4];
#pragma unroll
            for (int nt = 0; nt < 4; nt++) {
                const int row = brows[nt];
                ldm_x4(bt[nt][0], bt[nt][1], bt[nt][2], bt[nt][3],
                       sB + row * 128 + ((chunk ^ (row & 7)) << 4));
            }
#pragma unroll
            for (int mt = 0; mt < 2; mt++)
#pragma unroll
                for (int j = 0; j < 8; j++) {
                    const int nt = j >> 1, h = j & 1;
                    mma_bf16(acc[mt][j][0], acc[mt][j][1], acc[mt][j][2], acc[mt][j][3],
                             a[mt][0], a[mt][1], a[mt][2], a[mt][3],
                             bt[nt][h], bt[nt][h + 2]);
                }
        }
        __syncthreads();
    }

    // ---- epilogue
    const float sc = scale_ptr ? (1.0f + scale_ptr[0]) : 1.0f;
#pragma unroll
    for (int mt = 0; mt < 2; mt++) {
        const int r = m0 + wm * 32 + mt * 16 + (lane >> 2);
#pragma unroll
        for (int j = 0; j < 8; j++) {
            const int cb = n0 + wn * 64 + j * 8 + 2 * (lane & 3);
            float2 v0 = make_float2(acc[mt][j][0] * sc, acc[mt][j][1] * sc);
            float2 v1 = make_float2(acc[mt][j][2] * sc, acc[mt][j][3] * sc);
            *(float2*)(C + (size_t)r * N + cb)       = v0;
            *(float2*)(C + (size_t)(r + 8) * N + cb) = v1;
        }
    }
}

// ---------------- ve gate + v update + attn gate ----------------------------
__global__ __launch_bounds__(128) void gates_kernel(
    const float* __restrict__ x, const float* __restrict__ ve,
    const float* __restrict__ wvg, const float* __restrict__ wag)
{
    const int bt  = blockIdx.x;
    const int tid = threadIdx.x;
    __shared__ float xs[32];
    __shared__ float sg[8];

    if (tid < 32) xs[tid] = x[(size_t)bt * CEMB + tid];
    __syncthreads();

    if (tid < 8) {
        float s = 0.f;
#pragma unroll
        for (int c = 0; c < 32; c++) s += xs[c] * wvg[c * 8 + tid];
        sg[tid] = 2.0f / (1.0f + __expf(-s));
    } else if (tid >= 32 && tid < 48) {
        int h = tid - 32;
        float s = 0.f;
#pragma unroll
        for (int c = 0; c < 12; c++) s += xs[c] * wag[c * 16 + h];
        g_ag[(size_t)bt * NH + h] = 1.0f / (1.0f + __expf(-s));
    }
    __syncthreads();

    for (int i = tid; i < KVC; i += 128)
        g_v[(size_t)bt * KVC + i] += sg[i >> 7] * ve[(size_t)bt * KVC + i];
}

// ---------------- k time-shift + RoPE + RMSNorm ------------------------------
__global__ __launch_bounds__(128) void ropenorm_kernel(
    const float* __restrict__ cosb, const float* __restrict__ sinb)
{
    const int gw   = blockIdx.x * 4 + (threadIdx.x >> 5);
    const int lane = threadIdx.x & 31;
    const int bt = gw / 24;
    const int hh = gw % 24;
    const int t  = bt % TSEQ;

    const float c0 = cosb[t * 64 + lane];
    const float c1 = cosb[t * 64 + lane + 32];
    const float s0 = sinb[t * 64 + lane];
    const float s1 = sinb[t * 64 + lane + 32];

    float t1a, t1b, t2a, t2b;
    float* dst;
    if (hh < 16) {
        const float* base = g_q + (size_t)bt * CEMB + hh * HD;
        t1a = base[lane];      t1b = base[lane + 32];
        t2a = base[64 + lane]; t2b = base[96 + lane];
        dst = g_qn + (size_t)bt * CEMB + hh * HD;
    } else {
        const int j = hh - 16;
        const float* base = g_k + (size_t)bt * KVC + j * HD;
        const int bt2 = (t == 0) ? bt : (bt - 1);
        const float* base2 = g_k + (size_t)bt2 * KVC + j * HD;
        t1a = base [lane];      t1b = base [lane + 32];
        t2a = base2[64 + lane]; t2b = base2[96 + lane];
        dst = g_kn + (size_t)bt * KVC + j * HD;
    }

    float o1a =  t1a * c0 + t2a * s0;
    float o1b =  t1b * c1 + t2b * s1;
    float o2a = -t1a * s0 + t2a * c0;
    float o2b = -t1b * s1 + t2b * c1;

    float ss = o1a * o1a + o1b * o1b + o2a * o2a + o2b * o2b;
#pragma unroll
    for (int o = 16; o > 0; o >>= 1) ss += __shfl_xor_sync(0xffffffffu, ss, o);
    const float r = rsqrtf(ss * (1.0f / 128.0f) + 1.1920929e-7f);

    dst[lane]      = o1a * r;
    dst[lane + 32] = o1b * r;
    dst[64 + lane] = o2a * r;
    dst[96 + lane] = o2b * r;
}

// ---------------- sliding-window GQA flash attention -------------------------
__global__ __launch_bounds__(128) void attn_kernel(const int* __restrict__ wsp)
{
    __shared__ float Ksm[32 * 128];
    __shared__ float Vsm[32 * 128];

    const int tile = blockIdx.x;
    const int bh   = blockIdx.y;
    const int b = bh / NH, h = bh % NH;
    const int kvh = h >> 1;
    const int tid = threadIdx.x;
    const int row = tid >> 1;
    const int dh  = (tid & 1) * 64;
    const int q0  = tile * 64;
    const int qi  = q0 + row;

    int WS = wsp[0];
    if (WS <= 0 || WS > (1 << 20)) WS = 1024;
    const float scale = 0.088388347648318447f;

    float qreg[64];
    const float* qp = g_qn + (size_t)(b * TSEQ + qi) * CEMB + h * HD + dh;
#pragma unroll
    for (int i = 0; i < 64; i += 4) *(float4*)(qreg + i) = *(const float4*)(qp + i);

    float acc[64];
#pragma unroll
    for (int i = 0; i < 64; i++) acc[i] = 0.f;
    float m = -INFINITY, l = 0.f;

    int kmin = q0 - WS; if (kmin < 0) kmin = 0;
    const int kt0 = kmin & ~31;

    for (int kt = kt0; kt <= q0 + 63; kt += 32) {
        __syncthreads();
        {
            const float* Kb = g_kn + (size_t)(b * TSEQ + kt) * KVC + kvh * HD;
            const float* Vb = g_v  + (size_t)(b * TSEQ + kt) * KVC + kvh * HD;
#pragma unroll
            for (int i = 0; i < 8; i++) {
                const int f = (i * 128 + tid) * 4;
                const int r = f >> 7, cc = f & 127;
                *(float4*)(Ksm + f) = *(const float4*)(Kb + (size_t)r * KVC + cc);
                *(float4*)(Vsm + f) = *(const float4*)(Vb + (size_t)r * KVC + cc);
            }
        }
        __syncthreads();

        for (int j = 0; j < 32; j++) {
            const int kj = kt + j;
            const bool valid = (kj <= qi) && (kj >= qi - WS);
            if (__all_sync(0xffffffffu, !valid)) continue;

            const float4* kr4 = (const float4*)(Ksm + j * 128 + dh);
            float sp0 = 0.f, sp1 = 0.f, sp2 = 0.f, sp3 = 0.f;
#pragma unroll
            for (int i = 0; i < 16; i++) {
                float4 kv = kr4[i];
                sp0 += qreg[4 * i]     * kv.x;
                sp1 += qreg[4 * i + 1] * kv.y;
                sp2 += qreg[4 * i + 2] * kv.z;
                sp3 += qreg[4 * i + 3] * kv.w;
            }
            float s = (sp0 + sp1) + (sp2 + sp3);
            s += __shfl_xor_sync(0xffffffffu, s, 1);
            if (!valid) continue;

            s *= scale;
            if (s > m) {
                const float corr = __expf(m - s);
                m = s;
                l *= corr;
#pragma unroll
                for (int i = 0; i < 64; i++) acc[i] *= corr;
            }
            const float p = __expf(s - m);
            l += p;
            const float4* vr4 = (const float4*)(Vsm + j * 128 + dh);
#pragma unroll
            for (int i = 0; i < 16; i++) {
                float4 vv = vr4[i];
                acc[4 * i]     += p * vv.x;
                acc[4 * i + 1] += p * vv.y;
                acc[4 * i + 2] += p * vv.z;
                acc[4 * i + 3] += p * vv.w;
            }
        }
    }

    const float ag  = g_ag[(size_t)(b * TSEQ + qi) * NH + h];
    const float inv = ag / l;
    float* yp = g_y + (size_t)(b * TSEQ + qi) * CEMB + h * HD + dh;
#pragma unroll
    for (int i = 0; i < 64; i++) yp[i] = acc[i] * inv;
}

// ---------------- launcher ---------------------------------------------------
extern "C" void kernel_launch(void* const* d_in, const int* in_sizes, int n_in,
                              void* d_out, int out_size)
{
    const float* x     = (const float*)d_in[0];
    const float* ve    = (const float*)d_in[1];
    const float* cosb  = (const float*)d_in[2];
    const float* sinb  = (const float*)d_in[3];
    const float* wq    = (const float*)d_in[4];
    const float* wk    = (const float*)d_in[5];
    const float* wv    = (const float*)d_in[6];
    const float* wproj = (const float*)d_in[7];
    const float* wvg   = (const float*)d_in[8];
    const float* wag   = (const float*)d_in[9];
    const float* ps    = (const float*)d_in[10];
    const int*   wsp   = (const int*)  d_in[11];
    float* out = (float*)d_out;

    float *pq, *pk, *pv, *py;
    __nv_bfloat16 *px2, *py2, *pwqt, *pwkt, *pwvt, *pwpt;
    cudaGetSymbolAddress((void**)&pq,  g_q);
    cudaGetSymbolAddress((void**)&pk,  g_k);
    cudaGetSymbolAddress((void**)&pv,  g_v);
    cudaGetSymbolAddress((void**)&py,  g_y);
    cudaGetSymbolAddress((void**)&px2, g_x2);
    cudaGetSymbolAddress((void**)&py2, g_y2);
    cudaGetSymbolAddress((void**)&pwqt, g_wqt);
    cudaGetSymbolAddress((void**)&pwkt, g_wkt);
    cudaGetSymbolAddress((void**)&pwvt, g_wvt);
    cudaGetSymbolAddress((void**)&pwpt, g_wpt);

    cudaFuncSetAttribute(mma_gemm, cudaFuncAttributeMaxDynamicSharedMemorySize, GSMEM_TOT);

    // operand conversion
    conv_split<<<MROWS * CEMB / 1024, 256>>>(x, px2);
    conv_wt<<<dim3(CEMB / 32, CEMB / 32), dim3(32, 8)>>>(wq, pwqt, CEMB);
    conv_wt<<<dim3(KVC  / 32, CEMB / 32), dim3(32, 8)>>>(wk, pwkt, KVC);
    conv_wt<<<dim3(KVC  / 32, CEMB / 32), dim3(32, 8)>>>(wv, pwvt, KVC);
    conv_wt<<<dim3(CEMB / 32, CEMB / 32), dim3(32, 8)>>>(wproj, pwpt, CEMB);

    // QKV projections (mma.sync split-bf16)
    mma_gemm<<<dim3(CEMB / 128, MROWS / 128), 256, GSMEM_TOT>>>(px2, pwqt, pq, CEMB, nullptr);
    mma_gemm<<<dim3(KVC  / 128, MROWS / 128), 256, GSMEM_TOT>>>(px2, pwkt, pk, KVC, nullptr);
    mma_gemm<<<dim3(KVC  / 128, MROWS / 128), 256, GSMEM_TOT>>>(px2, pwvt, pv, KVC, nullptr);

    gates_kernel<<<MROWS, 128>>>(x, ve, wvg, wag);
    ropenorm_kernel<<<MROWS * 24 / 4, 128>>>(cosb, sinb);
    attn_kernel<<<dim3(TSEQ / 64, BATCH * NH), 128>>>(wsp);

    // output projection
    conv_split<<<MROWS * CEMB / 1024, 256>>>(py, py2);
    mma_gemm<<<dim3(CEMB / 128, MROWS / 128), 256, GSMEM_TOT>>>(py2, pwpt, out, CEMB, ps);
}